// round 4
// baseline (speedup 1.0000x reference)
#include <cuda_runtime.h>
#include <math.h>

typedef unsigned long long ull;

#define NQ 20000
#define KN 32
#define FULLM 0xffffffffu

__device__ float g_pm[NQ * 64];

// ---------- packed f32x2 helpers ----------
__device__ __forceinline__ ull pk2(float lo, float hi) {
    ull r; asm("mov.b64 %0, {%1, %2};" : "=l"(r) : "f"(lo), "f"(hi)); return r;
}
__device__ __forceinline__ void upk2(ull v, float& lo, float& hi) {
    asm("mov.b64 {%0, %1}, %2;" : "=f"(lo), "=f"(hi) : "l"(v));
}
__device__ __forceinline__ ull fma2(ull a, ull b, ull c) {
    ull d; asm("fma.rn.f32x2 %0, %1, %2, %3;" : "=l"(d) : "l"(a), "l"(b), "l"(c)); return d;
}

__device__ __forceinline__ float fast_atan2_pi(float y, float x) {
    float ax = fabsf(x);
    float mx = fmaxf(ax, y);
    float mn = fminf(ax, y);
    float a = __fdividef(mn, fmaxf(mx, 1e-38f));
    float s = a * a;
    float r = -0.01172120f;
    r = fmaf(r, s, 0.05265332f);
    r = fmaf(r, s, -0.11643287f);
    r = fmaf(r, s, 0.19354346f);
    r = fmaf(r, s, -0.33262347f);
    r = fmaf(r, s, 0.99997726f);
    r = r * a;
    r = (y > ax) ? (1.57079632679f - r) : r;
    r = (x < 0.f) ? (3.14159265359f - r) : r;
    return r * 0.31830988618379067f;
}

__device__ __forceinline__ float angle_pi(float axx, float ayy, float azz,
                                          float bxx, float byy, float bzz) {
    float dt = axx * bxx + ayy * byy + azz * bzz;
    float cx = ayy * bzz - azz * byy;
    float cy = azz * bxx - axx * bzz;
    float cz = axx * byy - ayy * bxx;
    float xn = sqrtf(cx * cx + cy * cy + cz * cz);
    return fast_atan2_pi(xn, dt);
}

// =============== Kernel A: PPF -> L1 -> L2 -> mean -> L3 (pm) ===============
#define A_THREADS 640
#define A_NWARP 20
#define A_STEP (148 * A_NWARP)
#define A_SW1 0
#define A_SB1 256
#define A_SB2 320
#define A_SB3 384
#define A_W2T 448                 // 64 x 68 [i*68+j]
#define A_W3T 4800                // 64 x 68 [i*68+o]
#define A_WARP 9152               // per warp: hd 544 ull (1088 floats)
#define A_SMF (A_WARP + A_NWARP * 1088)

__global__ __launch_bounds__(A_THREADS, 1)
void ppf_mlp_kernel(const float* __restrict__ q_pts,
                    const float* __restrict__ s_pts,
                    const int* __restrict__ nbr,
                    const float* __restrict__ normals,
                    const float* __restrict__ W1, const float* __restrict__ b1,
                    const float* __restrict__ W2, const float* __restrict__ b2,
                    const float* __restrict__ W3, const float* __restrict__ b3) {
    extern __shared__ float sm[];
    const int tid = threadIdx.x;
    for (int i = tid; i < 256; i += A_THREADS) sm[A_SW1 + i] = W1[i];
    for (int i = tid; i < 64; i += A_THREADS) {
        sm[A_SB1 + i] = b1[i]; sm[A_SB2 + i] = b2[i]; sm[A_SB3 + i] = b3[i];
    }
    for (int l = tid; l < 4096; l += A_THREADS) {
        int j = l >> 6, i = l & 63;
        sm[A_W2T + i * 68 + j] = W2[l];
    }
    for (int l = tid; l < 4096; l += A_THREADS) {
        int o = l >> 6, i = l & 63;
        sm[A_W3T + i * 68 + o] = W3[l];
    }
    __syncthreads();

    const int w = tid >> 5, lane = tid & 31;
    ull* hd = (ull*)(sm + A_WARP) + w * 544;   // [16][34] dup pairs
    float* shbf = (float*)hd;                  // reused after GEMM for hbar[64]
    const int j0 = (lane >> 2) * 8;
    const int k0 = (lane & 3) * 8;

    int q = blockIdx.x * A_NWARP + w;
    if (q >= NQ) return;
    int idxk = nbr[q * KN + lane];

    for (; q < NQ; q += A_STEP) {
        const int q_next = q + A_STEP;
        int idx_next = 0;
        if (q_next < NQ) idx_next = nbr[q_next * KN + lane];   // prefetch

        const int idx0 = __shfl_sync(FULLM, idxk, 0);
        const float px = q_pts[q * 3 + 0], py = q_pts[q * 3 + 1], pz = q_pts[q * 3 + 2];
        const float pnx = normals[idx0 * 3 + 0], pny = normals[idx0 * 3 + 1], pnz = normals[idx0 * 3 + 2];
        const float sx = s_pts[idxk * 3 + 0], sy = s_pts[idxk * 3 + 1], sz = s_pts[idxk * 3 + 2];
        const float nnx = normals[idxk * 3 + 0], nny = normals[idxk * 3 + 1], nnz = normals[idxk * 3 + 2];

        const float vx = sx - px, vy = sy - py, vz = sz - pz;
        const float dpp = sqrtf(vx * vx + vy * vy + vz * vz);
        const float a1 = angle_pi(pnx, pny, pnz, vx, vy, vz);
        const float a2 = angle_pi(nnx, nny, nnz, vx, vy, vz);
        const float a3 = angle_pi(pnx, pny, pnz, nnx, nny, nnz);

        float o8[8];

#pragma unroll
        for (int jh = 0; jh < 2; jh++) {
            const int j0h = j0 + 4 * jh;
            // 2 j-pairs x 8 k accumulators (16 ull = 32 regs)
            ull acc[2][8];
#pragma unroll
            for (int jp = 0; jp < 2; jp++) {
                ull b = *(const ull*)(sm + A_SB2 + j0h + 2 * jp);
#pragma unroll
                for (int kk = 0; kk < 8; kk++) acc[jp][kk] = b;
            }

#pragma unroll
            for (int p = 0; p < 4; p++) {
                // layer1 quarter, staged as duplicated pairs (recomputed per jh)
                const float4* w1v = (const float4*)(sm + A_SW1) + p * 16;
                const float* b1p = sm + A_SB1 + p * 16;
#pragma unroll
                for (int ii = 0; ii < 16; ii++) {
                    float4 wv = w1v[ii];
                    float v = b1p[ii];
                    v = fmaf(dpp, wv.x, v);
                    v = fmaf(a1, wv.y, v);
                    v = fmaf(a2, wv.z, v);
                    v = fmaf(a3, wv.w, v);
                    v = fmaxf(v, 0.f);
                    hd[ii * 34 + lane] = pk2(v, v);
                }
                __syncwarp();
#pragma unroll 4
                for (int ii = 0; ii < 16; ii++) {
                    const float* wr = sm + A_W2T + (p * 16 + ii) * 68 + j0h;
                    ulonglong2 wA = *(const ulonglong2*)wr;   // (j0h,j0h+1),(j0h+2,j0h+3)
                    const ull* hr = hd + ii * 34 + k0;
                    ulonglong2 h01 = *(const ulonglong2*)(hr);
                    ulonglong2 h23 = *(const ulonglong2*)(hr + 2);
                    ulonglong2 h45 = *(const ulonglong2*)(hr + 4);
                    ulonglong2 h67 = *(const ulonglong2*)(hr + 6);
                    ull hv[8] = {h01.x, h01.y, h23.x, h23.y, h45.x, h45.y, h67.x, h67.y};
#pragma unroll
                    for (int kk = 0; kk < 8; kk++) {
                        acc[0][kk] = fma2(wA.x, hv[kk], acc[0][kk]);
                        acc[1][kk] = fma2(wA.y, hv[kk], acc[1][kk]);
                    }
                }
                __syncwarp();
            }

            // relu + sum over this lane's 8 k
#pragma unroll
            for (int jp = 0; jp < 2; jp++) {
                float sl = 0.f, sh = 0.f;
#pragma unroll
                for (int kk = 0; kk < 8; kk++) {
                    float lo, hi; upk2(acc[jp][kk], lo, hi);
                    sl += fmaxf(lo, 0.f);
                    sh += fmaxf(hi, 0.f);
                }
                o8[4 * jh + 2 * jp] = sl;
                o8[4 * jh + 2 * jp + 1] = sh;
            }
        }

        // reduce across the 4 k-lanes, stash hbar to per-warp shared
#pragma unroll
        for (int u = 0; u < 8; u++) {
            o8[u] += __shfl_xor_sync(FULLM, o8[u], 1);
            o8[u] += __shfl_xor_sync(FULLM, o8[u], 2);
        }
        if ((lane & 3) == 0) {
            const float inv = 1.f / KN;
#pragma unroll
            for (int u = 0; u < 8; u++) shbf[j0 + u] = o8[u] * inv;
        }
        __syncwarp();

        // L3 on the mean: pm[64] -> global
        {
            float c0 = sm[A_SB3 + lane], c1 = sm[A_SB3 + lane + 32];
#pragma unroll 8
            for (int i = 0; i < 64; i++) {
                float hv = shbf[i];
                c0 = fmaf(hv, sm[A_W3T + i * 68 + lane], c0);
                c1 = fmaf(hv, sm[A_W3T + i * 68 + lane + 32], c1);
            }
            g_pm[q * 64 + lane] = c0;
            g_pm[q * 64 + lane + 32] = c1;
        }
        __syncwarp();   // shbf reused as hd next iteration
        idxk = idx_next;
    }
}

// ============ Kernel B: gather-mean + batched gate + Wv GEMM ============
#define B_WGT 0                   // 64*196 [j*196+o]
#define B_WVT 12544               // 64*196 [d*196+o]
#define B_BG  25088               // 192
#define B_PM  25280               // 64*33 [j*33+q]
#define B_GATE 27392              // 32*196 [q*196+o]
#define B_AGG 33664               // 16 warps * 256 ull; [d*4+t] packed (q0,q1)
#define B_SMF (B_AGG + 16 * 512)

__global__ __launch_bounds__(512, 1)
void gate_out_kernel(const float* __restrict__ s_feats,
                     const int* __restrict__ nbr,
                     const float* __restrict__ Wg, const float* __restrict__ bg,
                     const float* __restrict__ Wv,
                     float* __restrict__ out) {
    extern __shared__ float sm[];
    const int tid = threadIdx.x;
    for (int l = tid; l < 12288; l += 512) {
        int o = l >> 6, j = l & 63;
        sm[B_WGT + j * 196 + o] = Wg[l];
    }
    for (int l = tid; l < 12288; l += 512) {
        int o = l >> 6, d = l & 63;
        sm[B_WVT + d * 196 + o] = Wv[l];
    }
    for (int l = tid; l < 192; l += 512) sm[B_BG + l] = bg[l];
    __syncthreads();

    const int w = tid >> 5, lane = tid & 31;
    ull* ag = (ull*)(sm + B_AGG) + w * 256;

    for (int base = blockIdx.x * 32; base < NQ; base += 148 * 32) {
        // ---- gather-mean, both queries interleaved for MLP ----
        {
            const int q0 = base + w, q1 = base + w + 16;
            const int ridx0 = nbr[q0 * KN + lane];
            const int ridx1 = nbr[q1 * KN + lane];
            float2 p0a = {0,0}, p0b = {0,0}, p0c = {0,0};
            float2 p1a = {0,0}, p1b = {0,0}, p1c = {0,0};
#pragma unroll 4
            for (int k = 0; k < KN; k++) {
                int r0 = __shfl_sync(FULLM, ridx0, k);
                int r1 = __shfl_sync(FULLM, ridx1, k);
                const float2* b0 = (const float2*)(s_feats + (size_t)r0 * 192) + 3 * lane;
                const float2* b1 = (const float2*)(s_feats + (size_t)r1 * 192) + 3 * lane;
                float2 x0 = b0[0], y0 = b0[1], z0 = b0[2];
                float2 x1 = b1[0], y1 = b1[1], z1 = b1[2];
                p0a.x += x0.x; p0a.y += x0.y;
                p0b.x += y0.x; p0b.y += y0.y;
                p0c.x += z0.x; p0c.y += z0.y;
                p1a.x += x1.x; p1a.y += x1.y;
                p1b.x += y1.x; p1b.y += y1.y;
                p1c.x += z1.x; p1c.y += z1.y;
            }
            const float inv = 1.f / KN;
            const int d0 = 2 * lane;
            ag[d0 * 4 + 0] = pk2(p0a.x * inv, p1a.x * inv);
            ag[d0 * 4 + 1] = pk2(p0a.y * inv, p1a.y * inv);
            ag[d0 * 4 + 2] = pk2(p0b.x * inv, p1b.x * inv);
            ag[(d0 + 1) * 4 + 0] = pk2(p0b.y * inv, p1b.y * inv);
            ag[(d0 + 1) * 4 + 1] = pk2(p0c.x * inv, p1c.x * inv);
            ag[(d0 + 1) * 4 + 2] = pk2(p0c.y * inv, p1c.y * inv);
        }

        // ---- stage pm tile [64 j][32 q] ----
        {
            const float* psrc = g_pm + (size_t)base * 64;
            for (int e = tid; e < 2048; e += 512) {
                sm[B_PM + (e & 63) * 33 + (e >> 6)] = psrc[e];
            }
        }
        __syncthreads();   // B1

        // ---- gate batched: thread (q = tid&31, og) -> 12 o ----
        {
            const int ql = tid & 31, ob = (tid >> 5) * 12;
            ull ga[6];
#pragma unroll
            for (int s = 0; s < 6; s++) ga[s] = *(const ull*)(sm + B_BG + ob + 2 * s);
#pragma unroll 4
            for (int j = 0; j < 64; j++) {
                float pv = sm[B_PM + j * 33 + ql];
                ull pp = pk2(pv, pv);
                const float* wr = sm + B_WGT + j * 196 + ob;
                ulonglong2 wA = *(const ulonglong2*)wr;
                ulonglong2 wB = *(const ulonglong2*)(wr + 4);
                ulonglong2 wC = *(const ulonglong2*)(wr + 8);
                ga[0] = fma2(wA.x, pp, ga[0]); ga[1] = fma2(wA.y, pp, ga[1]);
                ga[2] = fma2(wB.x, pp, ga[2]); ga[3] = fma2(wB.y, pp, ga[3]);
                ga[4] = fma2(wC.x, pp, ga[4]); ga[5] = fma2(wC.y, pp, ga[5]);
            }
            float* gr = sm + B_GATE + ql * 196 + ob;
#pragma unroll
            for (int s = 0; s < 6; s++) {
                float lo, hi; upk2(ga[s], lo, hi);
                gr[2 * s + 0] = __fdividef(1.f, 1.f + __expf(-lo));
                gr[2 * s + 1] = __fdividef(1.f, 1.f + __expf(-hi));
            }
        }
        __syncthreads();   // B2

        // ---- Wv GEMM, (q0,q1) packed in f32x2 lanes; gate; store ----
        {
            const int ob = lane * 6;
            ull acc2[6][3];
#pragma unroll
            for (int oo = 0; oo < 6; oo++)
#pragma unroll
                for (int t = 0; t < 3; t++) acc2[oo][t] = 0ull;
#pragma unroll 2
            for (int d = 0; d < 64; d++) {
                const float* wp = sm + B_WVT + d * 196 + ob;
                float2 w01 = *(const float2*)wp;
                float2 w23 = *(const float2*)(wp + 2);
                float2 w45 = *(const float2*)(wp + 4);
                ulonglong2 t01 = *(const ulonglong2*)(ag + d * 4);
                ull t2 = ag[d * 4 + 2];
                float wv6[6] = {w01.x, w01.y, w23.x, w23.y, w45.x, w45.y};
#pragma unroll
                for (int oo = 0; oo < 6; oo++) {
                    ull wd = pk2(wv6[oo], wv6[oo]);
                    acc2[oo][0] = fma2(wd, t01.x, acc2[oo][0]);
                    acc2[oo][1] = fma2(wd, t01.y, acc2[oo][1]);
                    acc2[oo][2] = fma2(wd, t2, acc2[oo][2]);
                }
            }
            float* outr0 = out + (size_t)(base + w) * 576;
            float* outr1 = out + (size_t)(base + w + 16) * 576;
#pragma unroll
            for (int oo = 0; oo < 6; oo++) {
                const int o = ob + oo;
                float g0 = sm[B_GATE + w * 196 + o];
                float g1 = sm[B_GATE + (w + 16) * 196 + o];
                float x0, x1, y0, y1, z0, z1;
                upk2(acc2[oo][0], x0, x1);
                upk2(acc2[oo][1], y0, y1);
                upk2(acc2[oo][2], z0, z1);
                outr0[o * 3 + 0] = x0 * g0;
                outr0[o * 3 + 1] = y0 * g0;
                outr0[o * 3 + 2] = z0 * g0;
                outr1[o * 3 + 0] = x1 * g1;
                outr1[o * 3 + 1] = y1 * g1;
                outr1[o * 3 + 2] = z1 * g1;
            }
        }
        // no trailing barrier: AGG is warp-private; PM/GATE writes of tile t+1
        // are ordered behind B1(t+1)/B2(t+1) which require all warps past here.
    }
}

extern "C" void kernel_launch(void* const* d_in, const int* in_sizes, int n_in,
                              void* d_out, int out_size) {
    const float* q_pts   = (const float*)d_in[0];
    const float* s_pts   = (const float*)d_in[1];
    const float* s_feats = (const float*)d_in[2];
    const int*   nbr     = (const int*)  d_in[3];
    const float* normals = (const float*)d_in[4];
    const float* W1 = (const float*)d_in[5];
    const float* b1 = (const float*)d_in[6];
    const float* W2 = (const float*)d_in[7];
    const float* b2 = (const float*)d_in[8];
    const float* W3 = (const float*)d_in[9];
    const float* b3 = (const float*)d_in[10];
    const float* Wg = (const float*)d_in[11];
    const float* bg = (const float*)d_in[12];
    const float* Wv = (const float*)d_in[13];
    float* out = (float*)d_out;

    size_t smemA = A_SMF * sizeof(float);   // ~124 KB
    size_t smemB = B_SMF * sizeof(float);   // ~167 KB
    cudaFuncSetAttribute(ppf_mlp_kernel,
                         cudaFuncAttributeMaxDynamicSharedMemorySize, (int)smemA);
    cudaFuncSetAttribute(gate_out_kernel,
                         cudaFuncAttributeMaxDynamicSharedMemorySize, (int)smemB);

    ppf_mlp_kernel<<<148, A_THREADS, smemA>>>(q_pts, s_pts, nbr, normals,
                                              W1, b1, W2, b2, W3, b3);
    gate_out_kernel<<<148, 512, smemB>>>(s_feats, nbr, Wg, bg, Wv, out);
}

// round 6
// speedup vs baseline: 1.8605x; 1.8605x over previous
#include <cuda_runtime.h>
#include <math.h>

typedef unsigned long long ull;

#define NQ 20000
#define KN 32
#define FULLM 0xffffffffu

__device__ float g_pm[NQ * 64];

// ---------- packed f32x2 helpers ----------
__device__ __forceinline__ ull pk2(float lo, float hi) {
    ull r; asm("mov.b64 %0, {%1, %2};" : "=l"(r) : "f"(lo), "f"(hi)); return r;
}
__device__ __forceinline__ void upk2(ull v, float& lo, float& hi) {
    asm("mov.b64 {%0, %1}, %2;" : "=f"(lo), "=f"(hi) : "l"(v));
}
__device__ __forceinline__ ull fma2(ull a, ull b, ull c) {
    ull d; asm("fma.rn.f32x2 %0, %1, %2, %3;" : "=l"(d) : "l"(a), "l"(b), "l"(c)); return d;
}

__device__ __forceinline__ float fast_atan2_pi(float y, float x) {
    float ax = fabsf(x);
    float mx = fmaxf(ax, y);
    float mn = fminf(ax, y);
    float a = __fdividef(mn, fmaxf(mx, 1e-38f));
    float s = a * a;
    float r = -0.01172120f;
    r = fmaf(r, s, 0.05265332f);
    r = fmaf(r, s, -0.11643287f);
    r = fmaf(r, s, 0.19354346f);
    r = fmaf(r, s, -0.33262347f);
    r = fmaf(r, s, 0.99997726f);
    r = r * a;
    r = (y > ax) ? (1.57079632679f - r) : r;
    r = (x < 0.f) ? (3.14159265359f - r) : r;
    return r * 0.31830988618379067f;
}

__device__ __forceinline__ float angle_pi(float axx, float ayy, float azz,
                                          float bxx, float byy, float bzz) {
    float dt = axx * bxx + ayy * byy + azz * bzz;
    float cx = ayy * bzz - azz * byy;
    float cy = azz * bxx - axx * bzz;
    float cz = axx * byy - ayy * bxx;
    float xn = sqrtf(cx * cx + cy * cy + cz * cz);
    return fast_atan2_pi(xn, dt);
}

// =============== Kernel A: PPF -> L1 -> L2 -> mean -> L3 (pm) ===============
#define A_SW1 0
#define A_SB1 256
#define A_SB2 320
#define A_SB3 384
#define A_W2T 448                 // 64 x 68 [i*68+j]
#define A_W3T 4800                // 64 x 68 [i*68+o]
#define A_WARP 9152               // per warp: hs 16 x 36 floats = 576
#define A_SMF (A_WARP + 16 * 576)

__global__ __launch_bounds__(512, 1)
void ppf_mlp_kernel(const float* __restrict__ q_pts,
                    const float* __restrict__ s_pts,
                    const int* __restrict__ nbr,
                    const float* __restrict__ normals,
                    const float* __restrict__ W1, const float* __restrict__ b1,
                    const float* __restrict__ W2, const float* __restrict__ b2,
                    const float* __restrict__ W3, const float* __restrict__ b3) {
    extern __shared__ float sm[];
    const int tid = threadIdx.x;
    for (int i = tid; i < 256; i += 512) sm[A_SW1 + i] = W1[i];
    for (int i = tid; i < 64; i += 512) {
        sm[A_SB1 + i] = b1[i]; sm[A_SB2 + i] = b2[i]; sm[A_SB3 + i] = b3[i];
    }
    for (int l = tid; l < 4096; l += 512) {
        int j = l >> 6, i = l & 63;
        sm[A_W2T + i * 68 + j] = W2[l];
    }
    for (int l = tid; l < 4096; l += 512) {
        int o = l >> 6, i = l & 63;
        sm[A_W3T + i * 68 + o] = W3[l];
    }
    __syncthreads();

    const int w = tid >> 5, lane = tid & 31;
    float* hs = sm + A_WARP + w * 576;   // [16][36] plain floats
    float* shbf = hs;                    // reused for hbar[64] after GEMM
    const int j0 = (lane >> 2) * 8;      // 8 j-groups of 8
    const int k0 = (lane & 3) * 8;       // 4 k-groups of 8

    int q = blockIdx.x * 16 + w;
    if (q >= NQ) return;
    int idxk = nbr[q * KN + lane];

    for (; q < NQ; q += 148 * 16) {
        const int q_next = q + 148 * 16;
        int idx_next = 0;
        if (q_next < NQ) idx_next = nbr[q_next * KN + lane];

        const int idx0 = __shfl_sync(FULLM, idxk, 0);
        const float px = q_pts[q * 3 + 0], py = q_pts[q * 3 + 1], pz = q_pts[q * 3 + 2];
        const float pnx = normals[idx0 * 3 + 0], pny = normals[idx0 * 3 + 1], pnz = normals[idx0 * 3 + 2];
        const float sx = s_pts[idxk * 3 + 0], sy = s_pts[idxk * 3 + 1], sz = s_pts[idxk * 3 + 2];
        const float nnx = normals[idxk * 3 + 0], nny = normals[idxk * 3 + 1], nnz = normals[idxk * 3 + 2];

        const float vx = sx - px, vy = sy - py, vz = sz - pz;
        const float dpp = sqrtf(vx * vx + vy * vy + vz * vz);
        const float a1 = angle_pi(pnx, pny, pnz, vx, vy, vz);
        const float a2 = angle_pi(nnx, nny, nnz, vx, vy, vz);
        const float a3 = angle_pi(pnx, pny, pnz, nnx, nny, nnz);

        // acc[jj][kp]: j = j0+jj, k-pair (k0+2kp, k0+2kp+1)
        ull acc[8][4];
#pragma unroll
        for (int jj = 0; jj < 8; jj++) {
            float bv = sm[A_SB2 + j0 + jj];
            ull bp = pk2(bv, bv);
#pragma unroll
            for (int kp = 0; kp < 4; kp++) acc[jj][kp] = bp;
        }

#pragma unroll
        for (int p = 0; p < 4; p++) {
            // layer1 quarter (16 i), staged as plain floats, lane = k
            const float4* w1v = (const float4*)(sm + A_SW1) + p * 16;
            const float* b1p = sm + A_SB1 + p * 16;
#pragma unroll
            for (int ii = 0; ii < 16; ii++) {
                float4 wv = w1v[ii];
                float v = b1p[ii];
                v = fmaf(dpp, wv.x, v);
                v = fmaf(a1, wv.y, v);
                v = fmaf(a2, wv.z, v);
                v = fmaf(a3, wv.w, v);
                hs[ii * 36 + lane] = fmaxf(v, 0.f);
            }
            __syncwarp();
#pragma unroll 4
            for (int ii = 0; ii < 16; ii++) {
                const float* wr = sm + A_W2T + (p * 16 + ii) * 68 + j0;
                float4 wa = *(const float4*)wr;
                float4 wb = *(const float4*)(wr + 4);
                const float* hr = hs + ii * 36 + k0;
                ulonglong2 hA = *(const ulonglong2*)hr;        // (k0,k0+1),(k0+2,k0+3)
                ulonglong2 hB = *(const ulonglong2*)(hr + 4);  // (k0+4..k0+7)
                ull h0 = hA.x, h1 = hA.y, h2 = hB.x, h3 = hB.y;
                float wvv[8] = {wa.x, wa.y, wa.z, wa.w, wb.x, wb.y, wb.z, wb.w};
#pragma unroll
                for (int jj = 0; jj < 8; jj++) {
                    ull wd = pk2(wvv[jj], wvv[jj]);   // dup in regs: ALU, not crossbar
                    acc[jj][0] = fma2(wd, h0, acc[jj][0]);
                    acc[jj][1] = fma2(wd, h1, acc[jj][1]);
                    acc[jj][2] = fma2(wd, h2, acc[jj][2]);
                    acc[jj][3] = fma2(wd, h3, acc[jj][3]);
                }
            }
            __syncwarp();
        }

        // relu + sum over this lane's 8 k
        float o8[8];
#pragma unroll
        for (int jj = 0; jj < 8; jj++) {
            float s = 0.f;
#pragma unroll
            for (int kp = 0; kp < 4; kp++) {
                float lo, hi; upk2(acc[jj][kp], lo, hi);
                s += fmaxf(lo, 0.f) + fmaxf(hi, 0.f);
            }
            o8[jj] = s;
        }
        // reduce across the 4 k-lanes of each j-group
#pragma unroll
        for (int u = 0; u < 8; u++) {
            o8[u] += __shfl_xor_sync(FULLM, o8[u], 1);
            o8[u] += __shfl_xor_sync(FULLM, o8[u], 2);
        }
        if ((lane & 3) == 0) {
            const float inv = 1.f / KN;
#pragma unroll
            for (int u = 0; u < 8; u++) shbf[j0 + u] = o8[u] * inv;
        }
        __syncwarp();

        // L3 on the mean: pm[64] -> global
        {
            float c0 = sm[A_SB3 + lane], c1 = sm[A_SB3 + lane + 32];
#pragma unroll 8
            for (int i = 0; i < 64; i++) {
                float hv = shbf[i];
                c0 = fmaf(hv, sm[A_W3T + i * 68 + lane], c0);
                c1 = fmaf(hv, sm[A_W3T + i * 68 + lane + 32], c1);
            }
            g_pm[q * 64 + lane] = c0;
            g_pm[q * 64 + lane + 32] = c1;
        }
        __syncwarp();   // shbf reused as hs next iteration
        idxk = idx_next;
    }
}

// ============ Kernel B: gather-mean (LDG.128) + batched gate + Wv GEMM ============
#define B_WGT 0                   // 64*196 [j*196+o]
#define B_WVT 12544               // 64*196 [d*196+o]
#define B_BG  25088               // 192
#define B_PM  25280               // 64*33 [j*33+q]
#define B_GATE 27392              // 32*196 [q*196+o]
#define B_SC  33664               // 16 warps * 768 floats (2 q x 96 float4)
#define B_AGG 45952               // 16 warps * 256 ull; [d*4+t] packed (q0,q1)
#define B_SMF (B_AGG + 16 * 512)

__global__ __launch_bounds__(512, 1)
void gate_out_kernel(const float* __restrict__ s_feats,
                     const int* __restrict__ nbr,
                     const float* __restrict__ Wg, const float* __restrict__ bg,
                     const float* __restrict__ Wv,
                     float* __restrict__ out) {
    extern __shared__ float sm[];
    const int tid = threadIdx.x;
    for (int l = tid; l < 12288; l += 512) {
        int o = l >> 6, j = l & 63;
        sm[B_WGT + j * 196 + o] = Wg[l];
    }
    for (int l = tid; l < 12288; l += 512) {
        int o = l >> 6, d = l & 63;
        sm[B_WVT + d * 196 + o] = Wv[l];
    }
    for (int l = tid; l < 192; l += 512) sm[B_BG + l] = bg[l];
    __syncthreads();

    const int w = tid >> 5, lane = tid & 31;
    float* sc = sm + B_SC + w * 768;                 // [2 q][96 float4]
    ull* ag = (ull*)(sm + B_AGG) + w * 256;

    // lane-static chunk offsets: 2 rows x 48 float4 per step; lane owns
    // chunks {lane, lane+32, lane+64}; chunk c<48 -> row a, else row b
    const int o0 = lane * 4;
    const int o1 = (lane < 16) ? (lane + 32) * 4 : (lane - 16) * 4;
    const bool c1a = (lane < 16);
    const int o2 = (lane + 16) * 4;

    for (int base = blockIdx.x * 32; base < NQ; base += 148 * 32) {
        // ---- gather-sum for queries q0 = base+w, q1 = base+w+16 ----
        {
            const int q0 = base + w, q1 = base + w + 16;
            const int ridx0 = nbr[q0 * KN + lane];
            const int ridx1 = nbr[q1 * KN + lane];
            float4 a00 = {0,0,0,0}, a01 = {0,0,0,0}, a02 = {0,0,0,0};
            float4 a10 = {0,0,0,0}, a11 = {0,0,0,0}, a12 = {0,0,0,0};
#pragma unroll 4
            for (int t = 0; t < 16; t++) {
                int r0a = __shfl_sync(FULLM, ridx0, 2 * t);
                int r0b = __shfl_sync(FULLM, ridx0, 2 * t + 1);
                int r1a = __shfl_sync(FULLM, ridx1, 2 * t);
                int r1b = __shfl_sync(FULLM, ridx1, 2 * t + 1);
                const float* ba0 = s_feats + (size_t)r0a * 192;
                const float* bb0 = s_feats + (size_t)r0b * 192;
                const float* ba1 = s_feats + (size_t)r1a * 192;
                const float* bb1 = s_feats + (size_t)r1b * 192;
                float4 v;
                v = *(const float4*)(ba0 + o0);
                a00.x += v.x; a00.y += v.y; a00.z += v.z; a00.w += v.w;
                v = *(const float4*)((c1a ? ba0 : bb0) + o1);
                a01.x += v.x; a01.y += v.y; a01.z += v.z; a01.w += v.w;
                v = *(const float4*)(bb0 + o2);
                a02.x += v.x; a02.y += v.y; a02.z += v.z; a02.w += v.w;
                v = *(const float4*)(ba1 + o0);
                a10.x += v.x; a10.y += v.y; a10.z += v.z; a10.w += v.w;
                v = *(const float4*)((c1a ? ba1 : bb1) + o1);
                a11.x += v.x; a11.y += v.y; a11.z += v.z; a11.w += v.w;
                v = *(const float4*)(bb1 + o2);
                a12.x += v.x; a12.y += v.y; a12.z += v.z; a12.w += v.w;
            }
            float4* s0v = (float4*)sc;          // query0: chunks 0..95
            float4* s1v = s0v + 96;             // query1
            s0v[lane] = a00; s0v[lane + 32] = a01; s0v[lane + 64] = a02;
            s1v[lane] = a10; s1v[lane + 32] = a11; s1v[lane + 64] = a12;
        }
        __syncwarp();
        // combine chunk pairs (f, f+192) -> ag[d*4+t] packed (q0,q1)
        {
            const float inv = 1.f / KN;
            const float* s0 = sc;
            const float* s1 = sc + 384;
#pragma unroll
            for (int u = 0; u < 6; u++) {
                int f = lane * 6 + u;
                float t0 = (s0[f] + s0[f + 192]) * inv;
                float t1 = (s1[f] + s1[f + 192]) * inv;
                ag[(2 * lane + u / 3) * 4 + (u % 3)] = pk2(t0, t1);
            }
        }

        // ---- stage pm tile [64 j][32 q] ----
        {
            const float* psrc = g_pm + (size_t)base * 64;
            for (int e = tid; e < 2048; e += 512) {
                sm[B_PM + (e & 63) * 33 + (e >> 6)] = psrc[e];
            }
        }
        __syncthreads();   // B1

        // ---- gate batched: thread (q = tid&31, og) -> 12 o ----
        {
            const int ql = tid & 31, ob = (tid >> 5) * 12;
            ull ga[6];
#pragma unroll
            for (int s = 0; s < 6; s++) ga[s] = *(const ull*)(sm + B_BG + ob + 2 * s);
#pragma unroll 4
            for (int j = 0; j < 64; j++) {
                float pv = sm[B_PM + j * 33 + ql];
                ull pp = pk2(pv, pv);
                const float* wr = sm + B_WGT + j * 196 + ob;
                ulonglong2 wA = *(const ulonglong2*)wr;
                ulonglong2 wB = *(const ulonglong2*)(wr + 4);
                ulonglong2 wC = *(const ulonglong2*)(wr + 8);
                ga[0] = fma2(wA.x, pp, ga[0]); ga[1] = fma2(wA.y, pp, ga[1]);
                ga[2] = fma2(wB.x, pp, ga[2]); ga[3] = fma2(wB.y, pp, ga[3]);
                ga[4] = fma2(wC.x, pp, ga[4]); ga[5] = fma2(wC.y, pp, ga[5]);
            }
            float* gr = sm + B_GATE + ql * 196 + ob;
#pragma unroll
            for (int s = 0; s < 6; s++) {
                float lo, hi; upk2(ga[s], lo, hi);
                gr[2 * s + 0] = __fdividef(1.f, 1.f + __expf(-lo));
                gr[2 * s + 1] = __fdividef(1.f, 1.f + __expf(-hi));
            }
        }
        __syncthreads();   // B2

        // ---- Wv GEMM, (q0,q1) packed in f32x2 lanes; gate; store ----
        {
            const int ob = lane * 6;
            ull acc2[6][3];
#pragma unroll
            for (int oo = 0; oo < 6; oo++)
#pragma unroll
                for (int t = 0; t < 3; t++) acc2[oo][t] = 0ull;
#pragma unroll 2
            for (int d = 0; d < 64; d++) {
                const float* wp = sm + B_WVT + d * 196 + ob;
                float2 w01 = *(const float2*)wp;
                float2 w23 = *(const float2*)(wp + 2);
                float2 w45 = *(const float2*)(wp + 4);
                ulonglong2 t01 = *(const ulonglong2*)(ag + d * 4);
                ull t2 = ag[d * 4 + 2];
                float wv6[6] = {w01.x, w01.y, w23.x, w23.y, w45.x, w45.y};
#pragma unroll
                for (int oo = 0; oo < 6; oo++) {
                    ull wd = pk2(wv6[oo], wv6[oo]);
                    acc2[oo][0] = fma2(wd, t01.x, acc2[oo][0]);
                    acc2[oo][1] = fma2(wd, t01.y, acc2[oo][1]);
                    acc2[oo][2] = fma2(wd, t2, acc2[oo][2]);
                }
            }
            float* outr0 = out + (size_t)(base + w) * 576;
            float* outr1 = out + (size_t)(base + w + 16) * 576;
#pragma unroll
            for (int oo = 0; oo < 6; oo++) {
                const int o = ob + oo;
                float g0 = sm[B_GATE + w * 196 + o];
                float g1 = sm[B_GATE + (w + 16) * 196 + o];
                float x0, x1, y0, y1, z0, z1;
                upk2(acc2[oo][0], x0, x1);
                upk2(acc2[oo][1], y0, y1);
                upk2(acc2[oo][2], z0, z1);
                outr0[o * 3 + 0] = x0 * g0;
                outr0[o * 3 + 1] = y0 * g0;
                outr0[o * 3 + 2] = z0 * g0;
                outr1[o * 3 + 0] = x1 * g1;
                outr1[o * 3 + 1] = y1 * g1;
                outr1[o * 3 + 2] = z1 * g1;
            }
        }
        // no trailing barrier needed: SC/AGG warp-private; PM writes of next
        // tile precede B1(next) which requires all warps past this point.
    }
}

extern "C" void kernel_launch(void* const* d_in, const int* in_sizes, int n_in,
                              void* d_out, int out_size) {
    const float* q_pts   = (const float*)d_in[0];
    const float* s_pts   = (const float*)d_in[1];
    const float* s_feats = (const float*)d_in[2];
    const int*   nbr     = (const int*)  d_in[3];
    const float* normals = (const float*)d_in[4];
    const float* W1 = (const float*)d_in[5];
    const float* b1 = (const float*)d_in[6];
    const float* W2 = (const float*)d_in[7];
    const float* b2 = (const float*)d_in[8];
    const float* W3 = (const float*)d_in[9];
    const float* b3 = (const float*)d_in[10];
    const float* Wg = (const float*)d_in[11];
    const float* bg = (const float*)d_in[12];
    const float* Wv = (const float*)d_in[13];
    float* out = (float*)d_out;

    size_t smemA = A_SMF * sizeof(float);   // ~73 KB
    size_t smemB = B_SMF * sizeof(float);   // ~217 KB
    cudaFuncSetAttribute(ppf_mlp_kernel,
                         cudaFuncAttributeMaxDynamicSharedMemorySize, (int)smemA);
    cudaFuncSetAttribute(gate_out_kernel,
                         cudaFuncAttributeMaxDynamicSharedMemorySize, (int)smemB);

    ppf_mlp_kernel<<<148, 512, smemA>>>(q_pts, s_pts, nbr, normals,
                                        W1, b1, W2, b2, W3, b3);
    gate_out_kernel<<<148, 512, smemB>>>(s_feats, nbr, Wg, bg, Wv, out);
}

// round 7
// speedup vs baseline: 2.0951x; 1.1261x over previous
#include <cuda_runtime.h>
#include <math.h>

typedef unsigned long long ull;

#define NQ 20000
#define KN 32
#define FULLM 0xffffffffu

__device__ float g_pm[NQ * 64];
__device__ float g_agg[NQ * 192];

// ---------- packed f32x2 helpers ----------
__device__ __forceinline__ ull pk2(float lo, float hi) {
    ull r; asm("mov.b64 %0, {%1, %2};" : "=l"(r) : "f"(lo), "f"(hi)); return r;
}
__device__ __forceinline__ void upk2(ull v, float& lo, float& hi) {
    asm("mov.b64 {%0, %1}, %2;" : "=f"(lo), "=f"(hi) : "l"(v));
}
__device__ __forceinline__ ull fma2(ull a, ull b, ull c) {
    ull d; asm("fma.rn.f32x2 %0, %1, %2, %3;" : "=l"(d) : "l"(a), "l"(b), "l"(c)); return d;
}

__device__ __forceinline__ float fast_atan2_pi(float y, float x) {
    float ax = fabsf(x);
    float mx = fmaxf(ax, y);
    float mn = fminf(ax, y);
    float a = __fdividef(mn, fmaxf(mx, 1e-38f));
    float s = a * a;
    float r = -0.01172120f;
    r = fmaf(r, s, 0.05265332f);
    r = fmaf(r, s, -0.11643287f);
    r = fmaf(r, s, 0.19354346f);
    r = fmaf(r, s, -0.33262347f);
    r = fmaf(r, s, 0.99997726f);
    r = r * a;
    r = (y > ax) ? (1.57079632679f - r) : r;
    r = (x < 0.f) ? (3.14159265359f - r) : r;
    return r * 0.31830988618379067f;
}

__device__ __forceinline__ float angle_pi(float axx, float ayy, float azz,
                                          float bxx, float byy, float bzz) {
    float dt = axx * bxx + ayy * byy + azz * bzz;
    float cx = ayy * bzz - azz * byy;
    float cy = azz * bxx - axx * bzz;
    float cz = axx * byy - ayy * bxx;
    float xn = sqrtf(cx * cx + cy * cy + cz * cz);
    return fast_atan2_pi(xn, dt);
}

// ======= Kernel 1: gather-mean + PPF -> L1 -> L2 -> mean -> L3 (fused) =======
#define F_SW1 0
#define F_SB1 256
#define F_SB2 320
#define F_SB3 384
#define F_W2T 448                 // 64 x 68 [i*68+j]
#define F_W3T 4800                // 64 x 68 [i*68+o]
#define F_WARP 9152               // per warp: 576 floats (gather sc / h-stage / hbar)
#define F_SMF (F_WARP + 16 * 576)

__global__ __launch_bounds__(512, 1)
void fused_kernel(const float* __restrict__ q_pts,
                  const float* __restrict__ s_pts,
                  const float* __restrict__ s_feats,
                  const int* __restrict__ nbr,
                  const float* __restrict__ normals,
                  const float* __restrict__ W1, const float* __restrict__ b1,
                  const float* __restrict__ W2, const float* __restrict__ b2,
                  const float* __restrict__ W3, const float* __restrict__ b3) {
    extern __shared__ float sm[];
    const int tid = threadIdx.x;
    for (int i = tid; i < 256; i += 512) sm[F_SW1 + i] = W1[i];
    for (int i = tid; i < 64; i += 512) {
        sm[F_SB1 + i] = b1[i]; sm[F_SB2 + i] = b2[i]; sm[F_SB3 + i] = b3[i];
    }
    for (int l = tid; l < 4096; l += 512) {
        int j = l >> 6, i = l & 63;
        sm[F_W2T + i * 68 + j] = W2[l];
    }
    for (int l = tid; l < 4096; l += 512) {
        int o = l >> 6, i = l & 63;
        sm[F_W3T + i * 68 + o] = W3[l];
    }
    __syncthreads();

    const int w = tid >> 5, lane = tid & 31;
    float* hs = sm + F_WARP + w * 576;   // [16][36] h-stage; also gather scratch; also hbar
    float* shbf = hs;
    const int j0 = (lane >> 5 == 0 ? (lane >> 2) * 8 : 0);  // (lane>>2)*8
    const int k0 = (lane & 3) * 8;

    // gather chunk offsets: per t, 2 rows x 48 float4 chunks; lane owns 3
    const int o0 = lane * 4;
    const int o1 = (lane < 16) ? (lane + 32) * 4 : (lane - 16) * 4;
    const bool c1a = (lane < 16);
    const int o2 = (lane + 16) * 4;

    int q = blockIdx.x * 16 + w;
    if (q >= NQ) return;
    int idxk = nbr[q * KN + lane];

    for (; q < NQ; q += 148 * 16) {
        const int q_next = q + 148 * 16;
        int idx_next = 0;
        if (q_next < NQ) idx_next = nbr[q_next * KN + lane];

        // ---------------- gather-sum of s_feats over K ----------------
        {
            float4 a0 = {0,0,0,0}, a1 = {0,0,0,0}, a2 = {0,0,0,0};
#pragma unroll 4
            for (int t = 0; t < 16; t++) {
                int ra = __shfl_sync(FULLM, idxk, 2 * t);
                int rb = __shfl_sync(FULLM, idxk, 2 * t + 1);
                const float* pa = s_feats + (size_t)ra * 192;
                const float* pb = s_feats + (size_t)rb * 192;
                float4 v;
                v = *(const float4*)(pa + o0);
                a0.x += v.x; a0.y += v.y; a0.z += v.z; a0.w += v.w;
                v = *(const float4*)((c1a ? pa : pb) + o1);
                a1.x += v.x; a1.y += v.y; a1.z += v.z; a1.w += v.w;
                v = *(const float4*)(pb + o2);
                a2.x += v.x; a2.y += v.y; a2.z += v.z; a2.w += v.w;
            }
            float4* sc4 = (float4*)hs;         // 96 float4 = 384 floats
            sc4[lane] = a0; sc4[lane + 32] = a1; sc4[lane + 64] = a2;
        }
        __syncwarp();
        // combine chunk pairs (f, f+192), write agg (mean) to global
        {
            const float inv = 1.f / KN;
            float* dst = g_agg + (size_t)q * 192 + lane * 6;
#pragma unroll
            for (int s = 0; s < 3; s++) {
                int f = lane * 6 + 2 * s;
                float v0 = (hs[f] + hs[f + 192]) * inv;
                float v1 = (hs[f + 1] + hs[f + 193]) * inv;
                *(float2*)(dst + 2 * s) = make_float2(v0, v1);
            }
        }
        __syncwarp();   // all combine reads done before hs is rewritten below

        // ---------------- PPF features ----------------
        const int idx0 = __shfl_sync(FULLM, idxk, 0);
        const float px = q_pts[q * 3 + 0], py = q_pts[q * 3 + 1], pz = q_pts[q * 3 + 2];
        const float pnx = normals[idx0 * 3 + 0], pny = normals[idx0 * 3 + 1], pnz = normals[idx0 * 3 + 2];
        const float sx = s_pts[idxk * 3 + 0], sy = s_pts[idxk * 3 + 1], sz = s_pts[idxk * 3 + 2];
        const float nnx = normals[idxk * 3 + 0], nny = normals[idxk * 3 + 1], nnz = normals[idxk * 3 + 2];

        const float vx = sx - px, vy = sy - py, vz = sz - pz;
        const float dpp = sqrtf(vx * vx + vy * vy + vz * vz);
        const float a1 = angle_pi(pnx, pny, pnz, vx, vy, vz);
        const float a2 = angle_pi(nnx, nny, nnz, vx, vy, vz);
        const float a3 = angle_pi(pnx, pny, pnz, nnx, nny, nnz);

        // ---------------- L2 GEMM: acc[jj][kp], k-pairs packed ----------------
        ull acc[8][4];
#pragma unroll
        for (int jj = 0; jj < 8; jj++) {
            float bv = sm[F_SB2 + j0 + jj];
            ull bp = pk2(bv, bv);
#pragma unroll
            for (int kp = 0; kp < 4; kp++) acc[jj][kp] = bp;
        }

#pragma unroll
        for (int p = 0; p < 4; p++) {
            const float4* w1v = (const float4*)(sm + F_SW1) + p * 16;
            const float* b1p = sm + F_SB1 + p * 16;
#pragma unroll
            for (int ii = 0; ii < 16; ii++) {
                float4 wv = w1v[ii];
                float v = b1p[ii];
                v = fmaf(dpp, wv.x, v);
                v = fmaf(a1, wv.y, v);
                v = fmaf(a2, wv.z, v);
                v = fmaf(a3, wv.w, v);
                hs[ii * 36 + lane] = fmaxf(v, 0.f);
            }
            __syncwarp();
#pragma unroll 4
            for (int ii = 0; ii < 16; ii++) {
                const float* wr = sm + F_W2T + (p * 16 + ii) * 68 + j0;
                float4 wa = *(const float4*)wr;
                float4 wb = *(const float4*)(wr + 4);
                const float* hr = hs + ii * 36 + k0;
                ulonglong2 hA = *(const ulonglong2*)hr;
                ulonglong2 hB = *(const ulonglong2*)(hr + 4);
                ull h0 = hA.x, h1 = hA.y, h2 = hB.x, h3 = hB.y;
                float wvv[8] = {wa.x, wa.y, wa.z, wa.w, wb.x, wb.y, wb.z, wb.w};
#pragma unroll
                for (int jj = 0; jj < 8; jj++) {
                    ull wd = pk2(wvv[jj], wvv[jj]);
                    acc[jj][0] = fma2(wd, h0, acc[jj][0]);
                    acc[jj][1] = fma2(wd, h1, acc[jj][1]);
                    acc[jj][2] = fma2(wd, h2, acc[jj][2]);
                    acc[jj][3] = fma2(wd, h3, acc[jj][3]);
                }
            }
            __syncwarp();
        }

        // relu + per-lane k-sum, then reduce across the 4 k-lanes
        float o8[8];
#pragma unroll
        for (int jj = 0; jj < 8; jj++) {
            float s = 0.f;
#pragma unroll
            for (int kp = 0; kp < 4; kp++) {
                float lo, hi; upk2(acc[jj][kp], lo, hi);
                s += fmaxf(lo, 0.f) + fmaxf(hi, 0.f);
            }
            o8[jj] = s;
        }
#pragma unroll
        for (int u = 0; u < 8; u++) {
            o8[u] += __shfl_xor_sync(FULLM, o8[u], 1);
            o8[u] += __shfl_xor_sync(FULLM, o8[u], 2);
        }
        if ((lane & 3) == 0) {
            const float inv = 1.f / KN;
#pragma unroll
            for (int u = 0; u < 8; u++) shbf[j0 + u] = o8[u] * inv;
        }
        __syncwarp();

        // L3 on the mean: pm[64] -> global
        {
            float c0 = sm[F_SB3 + lane], c1 = sm[F_SB3 + lane + 32];
#pragma unroll 8
            for (int i = 0; i < 64; i++) {
                float hv = shbf[i];
                c0 = fmaf(hv, sm[F_W3T + i * 68 + lane], c0);
                c1 = fmaf(hv, sm[F_W3T + i * 68 + lane + 32], c1);
            }
            g_pm[q * 64 + lane] = c0;
            g_pm[q * 64 + lane + 32] = c1;
        }
        __syncwarp();   // hbar reads done before next-iteration gather scratch
        idxk = idx_next;
    }
}

// ============ Kernel 2: batched gate + Wv GEMM + coalesced store ============
#define G_WGT 0                   // 64*196 [j*196+o]
#define G_WVT 12544               // 64*196 [d*196+o]
#define G_BG  25088               // 192
#define G_PM  25280               // 64*33 [j*33+q]
#define G_GATE 27392              // 32*196 [q*196+o]
#define G_AGG 33664               // 16 warps * 256 ull; [d*4+t] packed (q0,q1)
#define G_SC  41856               // 16 warps * 576 floats (store staging)
#define G_SMF (G_SC + 16 * 576)

__global__ __launch_bounds__(512, 1)
void gate_out_kernel(const float* __restrict__ Wg, const float* __restrict__ bg,
                     const float* __restrict__ Wv,
                     float* __restrict__ out) {
    extern __shared__ float sm[];
    const int tid = threadIdx.x;
    for (int l = tid; l < 12288; l += 512) {
        int o = l >> 6, j = l & 63;
        sm[G_WGT + j * 196 + o] = Wg[l];
    }
    for (int l = tid; l < 12288; l += 512) {
        int o = l >> 6, d = l & 63;
        sm[G_WVT + d * 196 + o] = Wv[l];
    }
    for (int l = tid; l < 192; l += 512) sm[G_BG + l] = bg[l];
    __syncthreads();

    const int w = tid >> 5, lane = tid & 31;
    ull* ag = (ull*)(sm + G_AGG) + w * 256;
    float* scw = sm + G_SC + w * 576;

    for (int base = blockIdx.x * 32; base < NQ; base += 148 * 32) {
        const int q0 = base + w, q1 = base + w + 16;

        // ---- stage agg pairs (q0,q1) into ag[d*4+t] ----
        {
            const float* g0 = g_agg + (size_t)q0 * 192 + lane * 6;
            const float* g1 = g_agg + (size_t)q1 * 192 + lane * 6;
#pragma unroll
            for (int u = 0; u < 6; u++) {
                ag[(2 * lane + u / 3) * 4 + (u % 3)] = pk2(g0[u], g1[u]);
            }
        }

        // ---- stage pm tile [64 j][32 q] ----
        {
            const float* psrc = g_pm + (size_t)base * 64;
            for (int e = tid; e < 2048; e += 512) {
                sm[G_PM + (e & 63) * 33 + (e >> 6)] = psrc[e];
            }
        }
        __syncthreads();   // B1

        // ---- gate batched: thread (q = tid&31, og) -> 12 o ----
        {
            const int ql = tid & 31, ob = (tid >> 5) * 12;
            ull ga[6];
#pragma unroll
            for (int s = 0; s < 6; s++) ga[s] = *(const ull*)(sm + G_BG + ob + 2 * s);
#pragma unroll 4
            for (int j = 0; j < 64; j++) {
                float pv = sm[G_PM + j * 33 + ql];
                ull pp = pk2(pv, pv);
                const float* wr = sm + G_WGT + j * 196 + ob;
                ulonglong2 wA = *(const ulonglong2*)wr;
                ulonglong2 wB = *(const ulonglong2*)(wr + 4);
                ulonglong2 wC = *(const ulonglong2*)(wr + 8);
                ga[0] = fma2(wA.x, pp, ga[0]); ga[1] = fma2(wA.y, pp, ga[1]);
                ga[2] = fma2(wB.x, pp, ga[2]); ga[3] = fma2(wB.y, pp, ga[3]);
                ga[4] = fma2(wC.x, pp, ga[4]); ga[5] = fma2(wC.y, pp, ga[5]);
            }
            float* gr = sm + G_GATE + ql * 196 + ob;
#pragma unroll
            for (int s = 0; s < 6; s++) {
                float lo, hi; upk2(ga[s], lo, hi);
                gr[2 * s + 0] = __fdividef(1.f, 1.f + __expf(-lo));
                gr[2 * s + 1] = __fdividef(1.f, 1.f + __expf(-hi));
            }
        }
        __syncthreads();   // B2

        // ---- Wv GEMM, (q0,q1) packed; gate; coalesced store via staging ----
        {
            const int ob = lane * 6;
            ull acc2[6][3];
#pragma unroll
            for (int oo = 0; oo < 6; oo++)
#pragma unroll
                for (int t = 0; t < 3; t++) acc2[oo][t] = 0ull;
#pragma unroll 2
            for (int d = 0; d < 64; d++) {
                const float* wp = sm + G_WVT + d * 196 + ob;
                float2 w01 = *(const float2*)wp;
                float2 w23 = *(const float2*)(wp + 2);
                float2 w45 = *(const float2*)(wp + 4);
                ulonglong2 t01 = *(const ulonglong2*)(ag + d * 4);
                ull t2 = ag[d * 4 + 2];
                float wv6[6] = {w01.x, w01.y, w23.x, w23.y, w45.x, w45.y};
#pragma unroll
                for (int oo = 0; oo < 6; oo++) {
                    ull wd = pk2(wv6[oo], wv6[oo]);
                    acc2[oo][0] = fma2(wd, t01.x, acc2[oo][0]);
                    acc2[oo][1] = fma2(wd, t01.y, acc2[oo][1]);
                    acc2[oo][2] = fma2(wd, t2, acc2[oo][2]);
                }
            }

            // q0: stage scaled values, then coalesced STG.128
#pragma unroll
            for (int oo = 0; oo < 6; oo++) {
                const int o = ob + oo;
                float g0 = sm[G_GATE + w * 196 + o];
                float x0, x1, y0, y1, z0, z1;
                upk2(acc2[oo][0], x0, x1);
                upk2(acc2[oo][1], y0, y1);
                upk2(acc2[oo][2], z0, z1);
                (void)x1; (void)y1; (void)z1;
                scw[o * 3 + 0] = x0 * g0;
                scw[o * 3 + 1] = y0 * g0;
                scw[o * 3 + 2] = z0 * g0;
            }
            __syncwarp();
            {
                const float4* s4 = (const float4*)scw;
                float4* o4 = (float4*)(out + (size_t)q0 * 576);
#pragma unroll
                for (int i = 0; i < 4; i++) o4[i * 32 + lane] = s4[i * 32 + lane];
                ((float2*)(out + (size_t)q0 * 576 + 512))[lane] =
                    ((const float2*)(scw + 512))[lane];
            }
            __syncwarp();

            // q1
#pragma unroll
            for (int oo = 0; oo < 6; oo++) {
                const int o = ob + oo;
                float g1 = sm[G_GATE + (w + 16) * 196 + o];
                float x0, x1, y0, y1, z0, z1;
                upk2(acc2[oo][0], x0, x1);
                upk2(acc2[oo][1], y0, y1);
                upk2(acc2[oo][2], z0, z1);
                (void)x0; (void)y0; (void)z0;
                scw[o * 3 + 0] = x1 * g1;
                scw[o * 3 + 1] = y1 * g1;
                scw[o * 3 + 2] = z1 * g1;
            }
            __syncwarp();
            {
                const float4* s4 = (const float4*)scw;
                float4* o4 = (float4*)(out + (size_t)q1 * 576);
#pragma unroll
                for (int i = 0; i < 4; i++) o4[i * 32 + lane] = s4[i * 32 + lane];
                ((float2*)(out + (size_t)q1 * 576 + 512))[lane] =
                    ((const float2*)(scw + 512))[lane];
            }
            __syncwarp();
        }
        // PM/GATE of next tile ordered behind its own B1/B2 barriers.
    }
}

extern "C" void kernel_launch(void* const* d_in, const int* in_sizes, int n_in,
                              void* d_out, int out_size) {
    const float* q_pts   = (const float*)d_in[0];
    const float* s_pts   = (const float*)d_in[1];
    const float* s_feats = (const float*)d_in[2];
    const int*   nbr     = (const int*)  d_in[3];
    const float* normals = (const float*)d_in[4];
    const float* W1 = (const float*)d_in[5];
    const float* b1 = (const float*)d_in[6];
    const float* W2 = (const float*)d_in[7];
    const float* b2 = (const float*)d_in[8];
    const float* W3 = (const float*)d_in[9];
    const float* b3 = (const float*)d_in[10];
    const float* Wg = (const float*)d_in[11];
    const float* bg = (const float*)d_in[12];
    const float* Wv = (const float*)d_in[13];
    float* out = (float*)d_out;

    size_t smem1 = F_SMF * sizeof(float);   // ~73 KB
    size_t smem2 = G_SMF * sizeof(float);   // ~204 KB
    cudaFuncSetAttribute(fused_kernel,
                         cudaFuncAttributeMaxDynamicSharedMemorySize, (int)smem1);
    cudaFuncSetAttribute(gate_out_kernel,
                         cudaFuncAttributeMaxDynamicSharedMemorySize, (int)smem2);

    fused_kernel<<<148, 512, smem1>>>(q_pts, s_pts, s_feats, nbr, normals,
                                      W1, b1, W2, b2, W3, b3);
    gate_out_kernel<<<148, 512, smem2>>>(Wg, bg, Wv, out);
}